// round 15
// baseline (speedup 1.0000x reference)
#include <cuda_runtime.h>
#include <math.h>
#include <stdint.h>

// ---------------------------------------------------------------------------
// SmallMLP ternary forward, v12: sparse-gather GEMM1, issue-slot-minimal loop.
//   h  = relu(x @ tern(w1)^T + b1)   -> exact fp32; only w2-live cols stored
//   s  = 127/max(h);  logits = (round(h*s) @ tern(w2)^T)/s + b2;  log_softmax
// v11 was issue-bound (81%) at 5.1 slots/nnz. v12: premultiplied u32 offsets
// (addressing = 1 IADD) + packed add.rn.f32x2 (1 instr accumulates both m) ->
// 3.25 slots/nnz; expected binder shifts to the smem crossbar (~163us/CTA).
// ---------------------------------------------------------------------------

#define B_     8192
#define DIN    784
#define DH     4096
#define DOUT   10

#define CAP_S  48                   // u32 entries per sign per neuron
#define NPER   96                   // u32 per neuron total (384 B)
#define KP     256                  // bytes per smem k-row (64 floats, m-tile)
#define ZOFF   (784 * 256)          // premultiplied zero-row offset
#define G1_TM  64
#define G1_SMEM (785 * KP)          // 200960 B -> 1 CTA/SM

#define NSPL   16

// Scratch (device globals: allocation-free rule)
__device__ float    g_xT[(size_t)DIN * B_];   // transposed input [k][m]
__device__ float    g_hT2[(size_t)DH * B_];   // compacted transposed hidden
__device__ unsigned g_off[DH * NPER];         // premultiplied offsets k*256
__device__ unsigned g_meta[DH];               // cp4 | cm4<<4 | (slot+1)<<8
__device__ int      g_slot[DH];               // compact w2 slot or -1
__device__ unsigned g_nzw2[DH];               // packed w2 signs per slot
__device__ int      g_nnzc;
__device__ float    g_logits[B_ * 16];
__device__ unsigned g_maxbits;

// ------------------------------ asm helpers -------------------------------
__device__ __forceinline__ uint32_t smem_u32(const void* p) {
    uint32_t a;
    asm("{ .reg .u64 t; cvta.to.shared.u64 t, %1; cvt.u32.u64 %0, t; }" : "=r"(a) : "l"(p));
    return a;
}
__device__ __forceinline__ unsigned long long lds64(uint32_t addr) {
    unsigned long long v;
    asm volatile("ld.shared.b64 %0, [%1];" : "=l"(v) : "r"(addr));
    return v;
}
// packed fp32 pair add (Blackwell f32x2 pipe) — exact lane-wise fp32 adds
__device__ __forceinline__ void addx2(unsigned long long& a, unsigned long long v) {
    asm("add.rn.f32x2 %0, %0, %1;" : "+l"(a) : "l"(v));
}

// ---------------------------------------------------------------------------
// x[m][k] -> xT[k][m]
__global__ void __launch_bounds__(256)
transpose_x_kernel(const float* __restrict__ x) {
    __shared__ float t[32][33];
    const int mb = blockIdx.x * 32;
    const int kb = blockIdx.y * 32;
    const int tx = threadIdx.x & 31;
    const int ty = threadIdx.x >> 5;
    #pragma unroll
    for (int r = ty; r < 32; r += 8) {
        int k = kb + tx;
        t[r][tx] = (k < DIN) ? __ldg(x + (size_t)(mb + r) * DIN + k) : 0.0f;
    }
    __syncthreads();
    #pragma unroll
    for (int r = ty; r < 32; r += 8) {
        int k = kb + r;
        if (k < DIN) g_xT[(size_t)k * B_ + mb + tx] = t[tx][r];
    }
}

// Deterministic w2 column compaction (single-block scan) + maxbits reset.
__global__ void __launch_bounds__(1024)
build_w2scan_kernel(const float* __restrict__ w2) {
    __shared__ unsigned s[1024];
    const int t = threadIdx.x;
    unsigned cw[4];
    unsigned c = 0;
    #pragma unroll
    for (int i = 0; i < 4; i++) {
        const int n = t * 4 + i;
        unsigned w = 0;
        #pragma unroll
        for (int o = 0; o < DOUT; o++) {
            float v = __ldg(w2 + (size_t)o * DH + n);
            if (v >  0.1f) w |= 1u << o;
            if (v < -0.1f) w |= 1u << (16 + o);
        }
        cw[i] = w;
        c += (w != 0);
    }
    s[t] = c;
    __syncthreads();
    #pragma unroll
    for (int off = 1; off < 1024; off <<= 1) {
        unsigned v = (t >= off) ? s[t - off] : 0;
        __syncthreads();
        s[t] += v;
        __syncthreads();
    }
    int slot = s[t] - c;
    #pragma unroll
    for (int i = 0; i < 4; i++) {
        const int n = t * 4 + i;
        if (cw[i]) { g_nzw2[slot] = cw[i]; g_slot[n] = slot; slot++; }
        else       { g_slot[n] = -1; }
    }
    if (t == 1023) g_nnzc = s[1023];
    if (t == 0)    g_maxbits = 0u;
}

// Build per-neuron sparse +/- premultiplied u32 offset lists (k*256), padded
// with ZOFF to a multiple of 4 (>=4). Packs metadata incl. w2 slot.
__global__ void __launch_bounds__(256)
build_w1_kernel(const float* __restrict__ w1) {
    int n = blockIdx.x * 8 + (threadIdx.x >> 5);
    if (n >= DH) return;
    int lane = threadIdx.x & 31;
    int cp = 0, cm = 0;
    unsigned* base = g_off + (size_t)n * NPER;
    for (int k0 = 0; k0 < DIN; k0 += 32) {
        int k = k0 + lane;
        float w = (k < DIN) ? w1[(size_t)n * DIN + k] : 0.0f;
        bool ip = (w > 0.1f);
        bool im = (w < -0.1f);
        unsigned bp = __ballot_sync(0xFFFFFFFFu, ip);
        unsigned bm = __ballot_sync(0xFFFFFFFFu, im);
        unsigned pre = (1u << lane) - 1u;
        if (ip) { int p = cp + __popc(bp & pre); if (p < CAP_S - 3) base[p] = (unsigned)(k * 256); }
        if (im) { int p = cm + __popc(bm & pre); if (p < CAP_S - 3) base[CAP_S + p] = (unsigned)(k * 256); }
        cp += __popc(bp);
        cm += __popc(bm);
    }
    cp = min(cp, CAP_S - 4);
    cm = min(cm, CAP_S - 4);
    int cpp = (cp + 3) & ~3; if (cpp == 0) cpp = 4;
    int cmp = (cm + 3) & ~3; if (cmp == 0) cmp = 4;
    if (lane < cpp - cp) base[cp + lane] = ZOFF;
    if (lane < cmp - cm) base[CAP_S + cm + lane] = ZOFF;
    if (lane == 0) {
        int slot = g_slot[n];
        g_meta[n] = (unsigned)(cpp >> 2) | ((unsigned)(cmp >> 2) << 4)
                  | ((unsigned)(slot + 1) << 8);
    }
}

__global__ void l2init_kernel() { g_logits[blockIdx.x * 512 + threadIdx.x] = 0.0f; }

// ---------------------------------------------------------------------------
// Sparse GEMM1: grid (128), 1024 threads, CTA owns 64 m-rows. x-tile loaded
// once (coalesced LDG.128 -> STS.128, k-major, 256B pitch); all 4096 neurons
// swept (warp: 128 neurons). Per nnz: IADD + LDS.64 + ADD.f32x2 (+1/4 LDG).
// ---------------------------------------------------------------------------
__global__ void __launch_bounds__(1024, 1)
gemm_sparse_kernel(const float* __restrict__ b1) {
    extern __shared__ float xs[];

    const int m0   = blockIdx.x * G1_TM;
    const int tid  = threadIdx.x;
    const int lane = tid & 31;
    const int wid  = tid >> 5;

    // x tile: 784 k-rows x 64 floats, coalesced LDG.128 -> STS.128
    {
        const float4 z4 = {0.f, 0.f, 0.f, 0.f};
        for (int v = tid; v < DIN * 16; v += 1024) {
            int r = v >> 4, c = v & 15;
            float4 t = __ldg((const float4*)(g_xT + (size_t)r * B_ + m0) + c);
            *(float4*)(xs + r * 64 + c * 4) = t;
        }
        if (tid < 16) *(float4*)(xs + DIN * 64 + tid * 4) = z4;   // zero row
    }
    __syncthreads();

    const uint32_t xb = smem_u32(xs) + lane * 8;
    float lmax = 0.0f;

    #pragma unroll 1
    for (int g = 0; g < 4; g++) {
        const int nb = wid * 128 + g * 32;
        const unsigned ml  = __ldg(&g_meta[nb + lane]);
        const float    b1l = __ldg(b1 + nb + lane);

        #pragma unroll 1
        for (int i = 0; i < 32; i++) {
            const int      n  = nb + i;
            const unsigned mm = __shfl_sync(0xFFFFFFFFu, ml, i);
            const float    bv = __shfl_sync(0xFFFFFFFFu, b1l, i);
            const int cp4  = mm & 15;
            const int cm4  = (mm >> 4) & 15;
            const int slot = (int)(mm >> 8) - 1;

            const uint4* lp = (const uint4*)(g_off + (size_t)n * NPER);
            const uint4* lm = (const uint4*)(g_off + (size_t)n * NPER + CAP_S);

            uint4 tp = __ldg(lp);      // cp4 >= 1 guaranteed
            uint4 tm = __ldg(lm);      // cm4 >= 1 guaranteed

            unsigned long long p0 = 0, p1 = 0, p2 = 0, p3 = 0;
            unsigned long long q0 = 0, q1 = 0, q2 = 0, q3 = 0;

            const int jmax = max(cp4, cm4);
            #pragma unroll 1
            for (int j = 0; j < jmax; j++) {
                const uint4 fp_ = tp;
                const uint4 fm_ = tm;
                if (j + 1 < cp4) tp = __ldg(lp + j + 1);
                if (j + 1 < cm4) tm = __ldg(lm + j + 1);
                if (j < cp4) {
                    addx2(p0, lds64(xb + fp_.x));
                    addx2(p1, lds64(xb + fp_.y));
                    addx2(p2, lds64(xb + fp_.z));
                    addx2(p3, lds64(xb + fp_.w));
                }
                if (j < cm4) {
                    addx2(q0, lds64(xb + fm_.x));
                    addx2(q1, lds64(xb + fm_.y));
                    addx2(q2, lds64(xb + fm_.z));
                    addx2(q3, lds64(xb + fm_.w));
                }
            }
            // pairwise combine (exact, same order as v11)
            addx2(p0, p2); addx2(p1, p3); addx2(p0, p1);
            addx2(q0, q2); addx2(q1, q3); addx2(q0, q1);
            float2 ps = *(float2*)&p0;
            float2 qs = *(float2*)&q0;
            float2 acc;
            acc.x = fmaxf(ps.x - qs.x + bv, 0.0f);
            acc.y = fmaxf(ps.y - qs.y + bv, 0.0f);
            lmax = fmaxf(lmax, fmaxf(acc.x, acc.y));
            if (slot >= 0)
                *(float2*)(g_hT2 + (size_t)slot * B_ + m0 + 2 * lane) = acc;
        }
    }

    // global max: warp reduce + one atomic per warp (nonneg float == uint order)
    #pragma unroll
    for (int o = 16; o; o >>= 1) lmax = fmaxf(lmax, __shfl_xor_sync(0xFFFFFFFFu, lmax, o));
    if (lane == 0) atomicMax(&g_maxbits, __float_as_uint(lmax));
}

// ---------------------------------------------------------------------------
// Layer 2 partial sums over compacted columns (exact integer accumulation).
// ---------------------------------------------------------------------------
__global__ void __launch_bounds__(512)
l2_partial_kernel() {
    const int m   = blockIdx.x * 512 + threadIdx.x;
    const int nn  = g_nnzc;
    const int per = (nn + NSPL - 1) / NSPL;
    const int c0  = blockIdx.y * per;
    const int c1  = min(c0 + per, nn);

    const float scale = 127.0f / __uint_as_float(g_maxbits);

    float acc[DOUT];
    #pragma unroll
    for (int o = 0; o < DOUT; o++) acc[o] = 0.0f;

    for (int c = c0; c < c1; c++) {
        const unsigned cw = __ldg(g_nzw2 + c);
        const float    v  = __ldg(g_hT2 + (size_t)c * B_ + m);
        const float    q  = fminf(rintf(v * scale), 127.0f);
        #pragma unroll
        for (int o = 0; o < DOUT; o++) {
            if (cw & (1u << o))        acc[o] += q;
            if (cw & (1u << (16 + o))) acc[o] -= q;
        }
    }
    #pragma unroll
    for (int o = 0; o < DOUT; o++)
        if (acc[o] != 0.0f) atomicAdd(&g_logits[m * 16 + o], acc[o]);
}

__global__ void __launch_bounds__(256)
softmax_kernel(const float* __restrict__ b2, float* __restrict__ out) {
    const int m = blockIdx.x * 256 + threadIdx.x;
    const float inv = __uint_as_float(g_maxbits) * (1.0f / 127.0f);

    float l[DOUT];
    float mx = -1e30f;
    #pragma unroll
    for (int o = 0; o < DOUT; o++) {
        l[o] = g_logits[m * 16 + o] * inv + __ldg(b2 + o);
        mx = fmaxf(mx, l[o]);
    }
    float s = 0.0f;
    #pragma unroll
    for (int o = 0; o < DOUT; o++) s += expf(l[o] - mx);
    const float ls = logf(s);
    #pragma unroll
    for (int o = 0; o < DOUT; o++) out[(size_t)m * DOUT + o] = l[o] - mx - ls;
}

// ---------------------------------------------------------------------------
extern "C" void kernel_launch(void* const* d_in, const int* in_sizes, int n_in,
                              void* d_out, int out_size) {
    const float* x  = (const float*)d_in[0];
    const float* w1 = (const float*)d_in[1];
    const float* b1 = (const float*)d_in[2];
    const float* w2 = (const float*)d_in[3];
    const float* b2 = (const float*)d_in[4];
    float* out = (float*)d_out;

    cudaFuncSetAttribute(gemm_sparse_kernel,
                         cudaFuncAttributeMaxDynamicSharedMemorySize, G1_SMEM);

    transpose_x_kernel<<<dim3(B_ / 32, (DIN + 31) / 32), 256>>>(x);  // launch 0
    build_w2scan_kernel<<<1, 1024>>>(w2);              // launch 1 (slots + maxbits)
    build_w1_kernel<<<DH / 8, 256>>>(w1);              // launch 2 (reads g_slot)
    gemm_sparse_kernel<<<B_ / G1_TM, 1024, G1_SMEM>>>(b1);  // launch 3 (ncu slot)
    l2init_kernel<<<(B_ * 16) / 512, 512>>>();         // launch 4
    l2_partial_kernel<<<dim3(B_ / 512, NSPL), 512>>>();            // launch 5
    softmax_kernel<<<B_ / 256, 256>>>(b2, out);        // launch 6
}

// round 16
// speedup vs baseline: 1.1416x; 1.1416x over previous
#include <cuda_runtime.h>
#include <math.h>
#include <stdint.h>

// ---------------------------------------------------------------------------
// SmallMLP ternary forward, v13: sparse-gather GEMM1, LSU-floor tuned.
//   h  = relu(x @ tern(w1)^T + b1)   -> exact fp32; only w2-live cols stored
//   s  = 127/max(h);  logits = (round(h*s) @ tern(w2)^T)/s + b2;  log_softmax
// Calibrated LSU model (v11/v12): binder = L1TEX = gather crossbar (2cyc/LDS.64)
// + list LDG dispatch + tile load. v13: u16 lists (min LDG count) + f32x2 adds
// (min issue) + 148 persistent CTAs sweeping 1024 (m-tile, neuron-group) units
// so the whole chip carries the crossbar traffic.
// ---------------------------------------------------------------------------

#define B_     8192
#define DIN    784
#define DH     4096
#define DOUT   10

#define CAP_S  48                   // u16 entries per sign per neuron (6 chunks)
#define NPER   96                   // u16 per neuron total (192 B)
#define ZOFF16 (784 * 32)           // u16 zero-row code (k*32), addr = code<<3
#define G1_SMEM (785 * 256)         // 200960 B x-tile (784 k-rows x 64 floats + zero row)

#define NCTA   148                  // persistent CTAs (one per SM)
#define NU     1024                 // 128 m-tiles x 8 neuron-groups (512 n each)

#define NSPL   16

// Scratch (device globals: allocation-free rule)
__device__ float          g_xT[(size_t)DIN * B_];   // transposed input [k][m]
__device__ float          g_hT2[(size_t)DH * B_];   // compacted transposed hidden
__device__ unsigned short g_idx[DH * NPER];         // u16 codes k*32, [48+|48-]
__device__ unsigned       g_meta[DH];               // cp8 | cm8<<4 | (slot+1)<<8
__device__ int            g_slot[DH];               // compact w2 slot or -1
__device__ unsigned       g_nzw2[DH];               // packed w2 signs per slot
__device__ int            g_nnzc;
__device__ float          g_logits[B_ * 16];
__device__ unsigned       g_maxbits;

// ------------------------------ asm helpers -------------------------------
__device__ __forceinline__ uint32_t smem_u32(const void* p) {
    uint32_t a;
    asm("{ .reg .u64 t; cvta.to.shared.u64 t, %1; cvt.u32.u64 %0, t; }" : "=r"(a) : "l"(p));
    return a;
}
__device__ __forceinline__ unsigned long long lds64(uint32_t addr) {
    unsigned long long v;
    asm volatile("ld.shared.b64 %0, [%1];" : "=l"(v) : "r"(addr));
    return v;
}
// packed fp32 pair add (Blackwell f32x2) — exact lane-wise fp32 adds
__device__ __forceinline__ void addx2(unsigned long long& a, unsigned long long v) {
    asm("add.rn.f32x2 %0, %0, %1;" : "+l"(a) : "l"(v));
}

// ---------------------------------------------------------------------------
// x[m][k] -> xT[k][m]
__global__ void __launch_bounds__(256)
transpose_x_kernel(const float* __restrict__ x) {
    __shared__ float t[32][33];
    const int mb = blockIdx.x * 32;
    const int kb = blockIdx.y * 32;
    const int tx = threadIdx.x & 31;
    const int ty = threadIdx.x >> 5;
    #pragma unroll
    for (int r = ty; r < 32; r += 8) {
        int k = kb + tx;
        t[r][tx] = (k < DIN) ? __ldg(x + (size_t)(mb + r) * DIN + k) : 0.0f;
    }
    __syncthreads();
    #pragma unroll
    for (int r = ty; r < 32; r += 8) {
        int k = kb + r;
        if (k < DIN) g_xT[(size_t)k * B_ + mb + tx] = t[tx][r];
    }
}

// Deterministic w2 column compaction (single-block scan) + maxbits reset.
__global__ void __launch_bounds__(1024)
build_w2scan_kernel(const float* __restrict__ w2) {
    __shared__ unsigned s[1024];
    const int t = threadIdx.x;
    unsigned cw[4];
    unsigned c = 0;
    #pragma unroll
    for (int i = 0; i < 4; i++) {
        const int n = t * 4 + i;
        unsigned w = 0;
        #pragma unroll
        for (int o = 0; o < DOUT; o++) {
            float v = __ldg(w2 + (size_t)o * DH + n);
            if (v >  0.1f) w |= 1u << o;
            if (v < -0.1f) w |= 1u << (16 + o);
        }
        cw[i] = w;
        c += (w != 0);
    }
    s[t] = c;
    __syncthreads();
    #pragma unroll
    for (int off = 1; off < 1024; off <<= 1) {
        unsigned v = (t >= off) ? s[t - off] : 0;
        __syncthreads();
        s[t] += v;
        __syncthreads();
    }
    int slot = s[t] - c;
    #pragma unroll
    for (int i = 0; i < 4; i++) {
        const int n = t * 4 + i;
        if (cw[i]) { g_nzw2[slot] = cw[i]; g_slot[n] = slot; slot++; }
        else       { g_slot[n] = -1; }
    }
    if (t == 1023) g_nnzc = s[1023];
    if (t == 0)    g_maxbits = 0u;
}

// Build per-neuron sparse +/- u16 code lists (code = k*32; addr = code<<3 with
// 256B k-pitch). Pads with ZOFF16 to a multiple of 8 (>= 8). Packs metadata.
__global__ void __launch_bounds__(256)
build_w1_kernel(const float* __restrict__ w1) {
    int n = blockIdx.x * 8 + (threadIdx.x >> 5);
    if (n >= DH) return;
    int lane = threadIdx.x & 31;
    int cp = 0, cm = 0;
    unsigned short* base = g_idx + (size_t)n * NPER;
    for (int k0 = 0; k0 < DIN; k0 += 32) {
        int k = k0 + lane;
        float w = (k < DIN) ? w1[(size_t)n * DIN + k] : 0.0f;
        bool ip = (w > 0.1f);
        bool im = (w < -0.1f);
        unsigned bp = __ballot_sync(0xFFFFFFFFu, ip);
        unsigned bm = __ballot_sync(0xFFFFFFFFu, im);
        unsigned pre = (1u << lane) - 1u;
        if (ip) { int p = cp + __popc(bp & pre); if (p < CAP_S - 7) base[p] = (unsigned short)(k * 32); }
        if (im) { int p = cm + __popc(bm & pre); if (p < CAP_S - 7) base[CAP_S + p] = (unsigned short)(k * 32); }
        cp += __popc(bp);
        cm += __popc(bm);
    }
    cp = min(cp, CAP_S - 8);
    cm = min(cm, CAP_S - 8);
    int cpp = (cp + 7) & ~7; if (cpp == 0) cpp = 8;
    int cmp = (cm + 7) & ~7; if (cmp == 0) cmp = 8;
    if (lane < cpp - cp) base[cp + lane] = ZOFF16;
    if (lane < cmp - cm) base[CAP_S + cm + lane] = ZOFF16;
    if (lane == 0) {
        int slot = g_slot[n];
        g_meta[n] = (unsigned)(cpp >> 3) | ((unsigned)(cmp >> 3) << 4)
                  | ((unsigned)(slot + 1) << 8);
    }
}

__global__ void l2init_kernel() { g_logits[blockIdx.x * 512 + threadIdx.x] = 0.0f; }

// ---------------------------------------------------------------------------
// Sparse GEMM1: 148 persistent CTAs, 1024 threads. Work units = (m-tile,
// neuron-group): 128 tiles x 8 groups of 512 neurons; CTA b owns units
// [b*NU/NCTA, (b+1)*NU/NCTA) in tile-major order (<=2 x-tile loads/CTA).
// Per nnz: extract+LEA (alu) + LDS.64 + add.f32x2 (+1/8 list LDG).
// ---------------------------------------------------------------------------
__global__ void __launch_bounds__(1024, 1)
gemm_sparse_kernel(const float* __restrict__ b1) {
    extern __shared__ float xs[];

    const int tid  = threadIdx.x;
    const int lane = tid & 31;
    const int wid  = tid >> 5;
    const int u0   = (blockIdx.x * NU) / NCTA;
    const int u1   = ((blockIdx.x + 1) * NU) / NCTA;

    const uint32_t xb = smem_u32(xs) + lane * 8;
    float lmax = 0.0f;
    int cur_tile = -1;
    int m0 = 0;

    #pragma unroll 1
    for (int u = u0; u < u1; u++) {
        const int tile = u >> 3;
        const int grp  = u & 7;

        if (tile != cur_tile) {
            if (cur_tile >= 0) __syncthreads();          // finish prior reads
            m0 = tile * 64;
            for (int v = tid; v < DIN * 16; v += 1024) { // coalesced tile load
                int r = v >> 4, c = v & 15;
                float4 t = __ldg((const float4*)(g_xT + (size_t)r * B_ + m0) + c);
                *(float4*)(xs + r * 64 + c * 4) = t;
            }
            if (tid < 16) *(float4*)(xs + DIN * 64 + tid * 4) = make_float4(0.f, 0.f, 0.f, 0.f);
            __syncthreads();
            cur_tile = tile;
        }

        const int nb = grp * 512 + wid * 16;             // 16 neurons per warp
        const unsigned ml  = __ldg(&g_meta[nb + (lane & 15)]);
        const float    b1l = __ldg(b1 + nb + (lane & 15));

        #pragma unroll 1
        for (int i = 0; i < 16; i++) {
            const int      n  = nb + i;
            const unsigned mm = __shfl_sync(0xFFFFFFFFu, ml, i);
            const float    bv = __shfl_sync(0xFFFFFFFFu, b1l, i);
            const int cp8  = mm & 15;
            const int cm8  = (mm >> 4) & 15;
            const int slot = (int)(mm >> 8) - 1;

            const uint4* lp = (const uint4*)(g_idx + (size_t)n * NPER);
            const uint4* lm = (const uint4*)(g_idx + (size_t)n * NPER + CAP_S);

            uint4 tp = __ldg(lp);      // cp8 >= 1 guaranteed
            uint4 tm = __ldg(lm);      // cm8 >= 1 guaranteed

            unsigned long long p0 = 0, p1 = 0, p2 = 0, p3 = 0;
            unsigned long long q0 = 0, q1 = 0, q2 = 0, q3 = 0;

            const int jmax = max(cp8, cm8);
            #pragma unroll 1
            for (int j = 0; j < jmax; j++) {
                const uint4 fp_ = tp;
                const uint4 fm_ = tm;
                if (j + 1 < cp8) tp = __ldg(lp + j + 1);
                if (j + 1 < cm8) tm = __ldg(lm + j + 1);
                if (j < cp8) {        // 8 gathers: code = k*32, addr = code<<3
                    addx2(p0, lds64(xb + ((fp_.x & 0xFFFFu) << 3)));
                    addx2(p1, lds64(xb + ((fp_.x >> 16) << 3)));
                    addx2(p2, lds64(xb + ((fp_.y & 0xFFFFu) << 3)));
                    addx2(p3, lds64(xb + ((fp_.y >> 16) << 3)));
                    addx2(p0, lds64(xb + ((fp_.z & 0xFFFFu) << 3)));
                    addx2(p1, lds64(xb + ((fp_.z >> 16) << 3)));
                    addx2(p2, lds64(xb + ((fp_.w & 0xFFFFu) << 3)));
                    addx2(p3, lds64(xb + ((fp_.w >> 16) << 3)));
                }
                if (j < cm8) {
                    addx2(q0, lds64(xb + ((fm_.x & 0xFFFFu) << 3)));
                    addx2(q1, lds64(xb + ((fm_.x >> 16) << 3)));
                    addx2(q2, lds64(xb + ((fm_.y & 0xFFFFu) << 3)));
                    addx2(q3, lds64(xb + ((fm_.y >> 16) << 3)));
                    addx2(q0, lds64(xb + ((fm_.z & 0xFFFFu) << 3)));
                    addx2(q1, lds64(xb + ((fm_.z >> 16) << 3)));
                    addx2(q2, lds64(xb + ((fm_.w & 0xFFFFu) << 3)));
                    addx2(q3, lds64(xb + ((fm_.w >> 16) << 3)));
                }
            }
            addx2(p0, p2); addx2(p1, p3); addx2(p0, p1);
            addx2(q0, q2); addx2(q1, q3); addx2(q0, q1);
            float2 ps = *(float2*)&p0;
            float2 qs = *(float2*)&q0;
            float2 acc;
            acc.x = fmaxf(ps.x - qs.x + bv, 0.0f);
            acc.y = fmaxf(ps.y - qs.y + bv, 0.0f);
            lmax = fmaxf(lmax, fmaxf(acc.x, acc.y));
            if (slot >= 0)
                *(float2*)(g_hT2 + (size_t)slot * B_ + m0 + 2 * lane) = acc;
        }
    }

    // global max: warp reduce + one atomic per warp (nonneg float == uint order)
    #pragma unroll
    for (int o = 16; o; o >>= 1) lmax = fmaxf(lmax, __shfl_xor_sync(0xFFFFFFFFu, lmax, o));
    if (lane == 0) atomicMax(&g_maxbits, __float_as_uint(lmax));
}

// ---------------------------------------------------------------------------
// Layer 2 partial sums over compacted columns (exact integer accumulation).
// ---------------------------------------------------------------------------
__global__ void __launch_bounds__(512)
l2_partial_kernel() {
    const int m   = blockIdx.x * 512 + threadIdx.x;
    const int nn  = g_nnzc;
    const int per = (nn + NSPL - 1) / NSPL;
    const int c0  = blockIdx.y * per;
    const int c1  = min(c0 + per, nn);

    const float scale = 127.0f / __uint_as_float(g_maxbits);

    float acc[DOUT];
    #pragma unroll
    for (int o = 0; o < DOUT; o++) acc[o] = 0.0f;

    for (int c = c0; c < c1; c++) {
        const unsigned cw = __ldg(g_nzw2 + c);
        const float    v  = __ldg(g_hT2 + (size_t)c * B_ + m);
        const float    q  = fminf(rintf(v * scale), 127.0f);
        #pragma unroll
        for (int o = 0; o < DOUT; o++) {
            if (cw & (1u << o))        acc[o] += q;
            if (cw & (1u << (16 + o))) acc[o] -= q;
        }
    }
    #pragma unroll
    for (int o = 0; o < DOUT; o++)
        if (acc[o] != 0.0f) atomicAdd(&g_logits[m * 16 + o], acc[o]);
}

__global__ void __launch_bounds__(256)
softmax_kernel(const float* __restrict__ b2, float* __restrict__ out) {
    const int m = blockIdx.x * 256 + threadIdx.x;
    const float inv = __uint_as_float(g_maxbits) * (1.0f / 127.0f);

    float l[DOUT];
    float mx = -1e30f;
    #pragma unroll
    for (int o = 0; o < DOUT; o++) {
        l[o] = g_logits[m * 16 + o] * inv + __ldg(b2 + o);
        mx = fmaxf(mx, l[o]);
    }
    float s = 0.0f;
    #pragma unroll
    for (int o = 0; o < DOUT; o++) s += expf(l[o] - mx);
    const float ls = logf(s);
    #pragma unroll
    for (int o = 0; o < DOUT; o++) out[(size_t)m * DOUT + o] = l[o] - mx - ls;
}

// ---------------------------------------------------------------------------
extern "C" void kernel_launch(void* const* d_in, const int* in_sizes, int n_in,
                              void* d_out, int out_size) {
    const float* x  = (const float*)d_in[0];
    const float* w1 = (const float*)d_in[1];
    const float* b1 = (const float*)d_in[2];
    const float* w2 = (const float*)d_in[3];
    const float* b2 = (const float*)d_in[4];
    float* out = (float*)d_out;

    cudaFuncSetAttribute(gemm_sparse_kernel,
                         cudaFuncAttributeMaxDynamicSharedMemorySize, G1_SMEM);

    transpose_x_kernel<<<dim3(B_ / 32, (DIN + 31) / 32), 256>>>(x);  // launch 0
    build_w2scan_kernel<<<1, 1024>>>(w2);              // launch 1 (slots + maxbits)
    build_w1_kernel<<<DH / 8, 256>>>(w1);              // launch 2 (reads g_slot)
    gemm_sparse_kernel<<<NCTA, 1024, G1_SMEM>>>(b1);   // launch 3 (ncu slot)
    l2init_kernel<<<(B_ * 16) / 512, 512>>>();         // launch 4
    l2_partial_kernel<<<dim3(B_ / 512, NSPL), 512>>>();            // launch 5
    softmax_kernel<<<B_ / 256, 256>>>(b2, out);        // launch 6
}

// round 17
// speedup vs baseline: 1.1818x; 1.0352x over previous
#include <cuda_runtime.h>
#include <math.h>
#include <stdint.h>

// ---------------------------------------------------------------------------
// SmallMLP ternary forward, v14: fully fused persistent kernel.
//   Phase 1: sparse-gather GEMM1 (v13 loop, crossbar-floor tuned)
//   grid-wide barrier (all CTAs resident: 200KB smem -> 1 CTA/SM)
//   Phase 2: quantize + layer2 + log_softmax, smem reduction, direct store.
// Exact fp32 datapath -> rel_err ~5e-5 (validated R12-R16).
// ---------------------------------------------------------------------------

#define B_     8192
#define DIN    784
#define DH     4096
#define DOUT   10

#define CAP_S  48                   // u16 entries per sign per neuron (6 chunks)
#define NPER   96                   // u16 per neuron total (192 B)
#define ZOFF16 (784 * 32)           // u16 zero-row code (k*32), addr = code<<3
#define G1_SMEM (785 * 256)         // 200960 B x-tile -> 1 CTA/SM everywhere

#define NU     1024                 // 128 m-tiles x 8 neuron-groups (512 n each)

// Scratch (device globals: allocation-free rule)
__device__ float          g_xT[(size_t)DIN * B_];   // transposed input [k][m]
__device__ float          g_hT2[(size_t)DH * B_];   // compacted transposed hidden
__device__ unsigned short g_idx[DH * NPER];         // u16 codes k*32, [48+|48-]
__device__ unsigned       g_meta[DH];               // cp8 | cm8<<4 | (slot+1)<<8
__device__ int            g_slot[DH];               // compact w2 slot or -1
__device__ unsigned       g_nzw2[DH];               // packed w2 signs per slot
__device__ int            g_nnzc;
__device__ unsigned       g_maxbits;
__device__ unsigned       g_bar;                    // grid barrier counter

// ------------------------------ asm helpers -------------------------------
__device__ __forceinline__ uint32_t smem_u32(const void* p) {
    uint32_t a;
    asm("{ .reg .u64 t; cvta.to.shared.u64 t, %1; cvt.u32.u64 %0, t; }" : "=r"(a) : "l"(p));
    return a;
}
__device__ __forceinline__ unsigned long long lds64(uint32_t addr) {
    unsigned long long v;
    asm volatile("ld.shared.b64 %0, [%1];" : "=l"(v) : "r"(addr));
    return v;
}
// packed fp32 pair add (Blackwell f32x2) — exact lane-wise fp32 adds
__device__ __forceinline__ void addx2(unsigned long long& a, unsigned long long v) {
    asm("add.rn.f32x2 %0, %0, %1;" : "+l"(a) : "l"(v));
}

// ---------------------------------------------------------------------------
// x[m][k] -> xT[k][m]
__global__ void __launch_bounds__(256)
transpose_x_kernel(const float* __restrict__ x) {
    __shared__ float t[32][33];
    const int mb = blockIdx.x * 32;
    const int kb = blockIdx.y * 32;
    const int tx = threadIdx.x & 31;
    const int ty = threadIdx.x >> 5;
    #pragma unroll
    for (int r = ty; r < 32; r += 8) {
        int k = kb + tx;
        t[r][tx] = (k < DIN) ? __ldg(x + (size_t)(mb + r) * DIN + k) : 0.0f;
    }
    __syncthreads();
    #pragma unroll
    for (int r = ty; r < 32; r += 8) {
        int k = kb + r;
        if (k < DIN) g_xT[(size_t)k * B_ + mb + tx] = t[tx][r];
    }
}

// Deterministic w2 column compaction (single-block scan) + per-replay resets.
__global__ void __launch_bounds__(1024)
build_w2scan_kernel(const float* __restrict__ w2) {
    __shared__ unsigned s[1024];
    const int t = threadIdx.x;
    unsigned cw[4];
    unsigned c = 0;
    #pragma unroll
    for (int i = 0; i < 4; i++) {
        const int n = t * 4 + i;
        unsigned w = 0;
        #pragma unroll
        for (int o = 0; o < DOUT; o++) {
            float v = __ldg(w2 + (size_t)o * DH + n);
            if (v >  0.1f) w |= 1u << o;
            if (v < -0.1f) w |= 1u << (16 + o);
        }
        cw[i] = w;
        c += (w != 0);
    }
    s[t] = c;
    __syncthreads();
    #pragma unroll
    for (int off = 1; off < 1024; off <<= 1) {
        unsigned v = (t >= off) ? s[t - off] : 0;
        __syncthreads();
        s[t] += v;
        __syncthreads();
    }
    int slot = s[t] - c;
    #pragma unroll
    for (int i = 0; i < 4; i++) {
        const int n = t * 4 + i;
        if (cw[i]) { g_nzw2[slot] = cw[i]; g_slot[n] = slot; slot++; }
        else       { g_slot[n] = -1; }
    }
    if (t == 1023) g_nnzc = s[1023];
    if (t == 0) { g_maxbits = 0u; g_bar = 0u; }
}

// Build per-neuron sparse +/- u16 code lists (code = k*32; addr = code<<3 with
// 256B k-pitch). Pads with ZOFF16 to a multiple of 8 (>= 8). Packs metadata.
__global__ void __launch_bounds__(256)
build_w1_kernel(const float* __restrict__ w1) {
    int n = blockIdx.x * 8 + (threadIdx.x >> 5);
    if (n >= DH) return;
    int lane = threadIdx.x & 31;
    int cp = 0, cm = 0;
    unsigned short* base = g_idx + (size_t)n * NPER;
    for (int k0 = 0; k0 < DIN; k0 += 32) {
        int k = k0 + lane;
        float w = (k < DIN) ? w1[(size_t)n * DIN + k] : 0.0f;
        bool ip = (w > 0.1f);
        bool im = (w < -0.1f);
        unsigned bp = __ballot_sync(0xFFFFFFFFu, ip);
        unsigned bm = __ballot_sync(0xFFFFFFFFu, im);
        unsigned pre = (1u << lane) - 1u;
        if (ip) { int p = cp + __popc(bp & pre); if (p < CAP_S - 7) base[p] = (unsigned short)(k * 32); }
        if (im) { int p = cm + __popc(bm & pre); if (p < CAP_S - 7) base[CAP_S + p] = (unsigned short)(k * 32); }
        cp += __popc(bp);
        cm += __popc(bm);
    }
    cp = min(cp, CAP_S - 8);
    cm = min(cm, CAP_S - 8);
    int cpp = (cp + 7) & ~7; if (cpp == 0) cpp = 8;
    int cmp = (cm + 7) & ~7; if (cmp == 0) cmp = 8;
    if (lane < cpp - cp) base[cp + lane] = ZOFF16;
    if (lane < cmp - cm) base[CAP_S + cm + lane] = ZOFF16;
    if (lane == 0) {
        int slot = g_slot[n];
        g_meta[n] = (unsigned)(cpp >> 3) | ((unsigned)(cmp >> 3) << 4)
                  | ((unsigned)(slot + 1) << 8);
    }
}

// ---------------------------------------------------------------------------
// Fused persistent kernel. Phase 1 = sparse GEMM1 over (m-tile, neuron-group)
// units; grid barrier; phase 2 = quantize + layer2 reduce + log_softmax.
// ---------------------------------------------------------------------------
__global__ void __launch_bounds__(1024, 1)
fused_kernel(const float* __restrict__ b1, const float* __restrict__ b2,
             float* __restrict__ out) {
    extern __shared__ float xs[];

    const int tid  = threadIdx.x;
    const int lane = tid & 31;
    const int wid  = tid >> 5;
    const int g    = gridDim.x;
    const int u0   = (blockIdx.x * NU) / g;
    const int u1   = ((blockIdx.x + 1) * NU) / g;

    const uint32_t xb = smem_u32(xs) + lane * 8;
    float lmax = 0.0f;
    int cur_tile = -1;
    int m0 = 0;

    // ========================= Phase 1: GEMM1 =========================
    #pragma unroll 1
    for (int u = u0; u < u1; u++) {
        const int tile = u >> 3;
        const int grp  = u & 7;

        if (tile != cur_tile) {
            if (cur_tile >= 0) __syncthreads();
            m0 = tile * 64;
            for (int v = tid; v < DIN * 16; v += 1024) {
                int r = v >> 4, c = v & 15;
                float4 t = __ldg((const float4*)(g_xT + (size_t)r * B_ + m0) + c);
                *(float4*)(xs + r * 64 + c * 4) = t;
            }
            if (tid < 16) *(float4*)(xs + DIN * 64 + tid * 4) = make_float4(0.f, 0.f, 0.f, 0.f);
            __syncthreads();
            cur_tile = tile;
        }

        const int nb = grp * 512 + wid * 16;
        const unsigned ml  = __ldg(&g_meta[nb + (lane & 15)]);
        const float    b1l = __ldg(b1 + nb + (lane & 15));

        #pragma unroll 1
        for (int i = 0; i < 16; i++) {
            const int      n  = nb + i;
            const unsigned mm = __shfl_sync(0xFFFFFFFFu, ml, i);
            const float    bv = __shfl_sync(0xFFFFFFFFu, b1l, i);
            const int cp8  = mm & 15;
            const int cm8  = (mm >> 4) & 15;
            const int slot = (int)(mm >> 8) - 1;

            const uint4* lp = (const uint4*)(g_idx + (size_t)n * NPER);
            const uint4* lm = (const uint4*)(g_idx + (size_t)n * NPER + CAP_S);

            uint4 tp = __ldg(lp);
            uint4 tm = __ldg(lm);

            unsigned long long p0 = 0, p1 = 0, p2 = 0, p3 = 0;
            unsigned long long q0 = 0, q1 = 0, q2 = 0, q3 = 0;

            const int jmax = max(cp8, cm8);
            #pragma unroll 1
            for (int j = 0; j < jmax; j++) {
                const uint4 fp_ = tp;
                const uint4 fm_ = tm;
                if (j + 1 < cp8) tp = __ldg(lp + j + 1);
                if (j + 1 < cm8) tm = __ldg(lm + j + 1);
                if (j < cp8) {
                    addx2(p0, lds64(xb + ((fp_.x & 0xFFFFu) << 3)));
                    addx2(p1, lds64(xb + ((fp_.x >> 16) << 3)));
                    addx2(p2, lds64(xb + ((fp_.y & 0xFFFFu) << 3)));
                    addx2(p3, lds64(xb + ((fp_.y >> 16) << 3)));
                    addx2(p0, lds64(xb + ((fp_.z & 0xFFFFu) << 3)));
                    addx2(p1, lds64(xb + ((fp_.z >> 16) << 3)));
                    addx2(p2, lds64(xb + ((fp_.w & 0xFFFFu) << 3)));
                    addx2(p3, lds64(xb + ((fp_.w >> 16) << 3)));
                }
                if (j < cm8) {
                    addx2(q0, lds64(xb + ((fm_.x & 0xFFFFu) << 3)));
                    addx2(q1, lds64(xb + ((fm_.x >> 16) << 3)));
                    addx2(q2, lds64(xb + ((fm_.y & 0xFFFFu) << 3)));
                    addx2(q3, lds64(xb + ((fm_.y >> 16) << 3)));
                    addx2(q0, lds64(xb + ((fm_.z & 0xFFFFu) << 3)));
                    addx2(q1, lds64(xb + ((fm_.z >> 16) << 3)));
                    addx2(q2, lds64(xb + ((fm_.w & 0xFFFFu) << 3)));
                    addx2(q3, lds64(xb + ((fm_.w >> 16) << 3)));
                }
            }
            addx2(p0, p2); addx2(p1, p3); addx2(p0, p1);
            addx2(q0, q2); addx2(q1, q3); addx2(q0, q1);
            float2 ps = *(float2*)&p0;
            float2 qs = *(float2*)&q0;
            float2 acc;
            acc.x = fmaxf(ps.x - qs.x + bv, 0.0f);
            acc.y = fmaxf(ps.y - qs.y + bv, 0.0f);
            lmax = fmaxf(lmax, fmaxf(acc.x, acc.y));
            if (slot >= 0)
                *(float2*)(g_hT2 + (size_t)slot * B_ + m0 + 2 * lane) = acc;
        }
    }

    #pragma unroll
    for (int o = 16; o; o >>= 1) lmax = fmaxf(lmax, __shfl_xor_sync(0xFFFFFFFFu, lmax, o));
    if (lane == 0) atomicMax(&g_maxbits, __float_as_uint(lmax));

    // ==================== grid-wide barrier ====================
    __syncthreads();
    if (tid == 0) {
        __threadfence();
        atomicAdd(&g_bar, 1u);
        while (atomicAdd(&g_bar, 0u) < (unsigned)g) { }
    }
    __syncthreads();
    __threadfence();

    // ============ Phase 2: quantize + layer2 + log_softmax ============
    const float maxh  = __uint_as_float(g_maxbits);
    const float scale = 127.0f / maxh;
    const float inv   = maxh * (1.0f / 127.0f);
    const int   nn    = g_nnzc;

    const int sp = tid >> 6;                 // 16 slot-splits
    const int mlc = tid & 63;                // m within 64-block
    const int c0 = sp * nn / 16;
    const int c1 = (sp + 1) * nn / 16;

    #pragma unroll 1
    for (int mb = blockIdx.x; mb < B_ / 64; mb += g) {
        const int m0p = mb * 64;

        float acc[DOUT];
        #pragma unroll
        for (int o = 0; o < DOUT; o++) acc[o] = 0.0f;

        #pragma unroll 1
        for (int c = c0; c < c1; c++) {
            const unsigned cw = __ldg(g_nzw2 + c);
            const float    v  = g_hT2[(size_t)c * B_ + m0p + mlc];
            const float    q  = fminf(rintf(v * scale), 127.0f);
            #pragma unroll
            for (int o = 0; o < DOUT; o++) {
                if (cw & (1u << o))        acc[o] += q;
                if (cw & (1u << (16 + o))) acc[o] -= q;
            }
        }
        __syncthreads();                     // xs free for reuse
        #pragma unroll
        for (int o = 0; o < DOUT; o++)
            xs[(sp * 64 + mlc) * DOUT + o] = acc[o];
        __syncthreads();

        if (tid < 64 * DOUT) {
            const int m = tid / DOUT, o = tid - m * DOUT;
            float s = 0.0f;
            #pragma unroll
            for (int k2 = 0; k2 < 16; k2++) s += xs[(k2 * 64 + m) * DOUT + o];
            xs[10240 + m * DOUT + o] = s * inv + __ldg(b2 + o);
        }
        __syncthreads();

        if (tid < 64) {
            float l[DOUT];
            float mx = -1e30f;
            #pragma unroll
            for (int o = 0; o < DOUT; o++) {
                l[o] = xs[10240 + tid * DOUT + o];
                mx = fmaxf(mx, l[o]);
            }
            float s = 0.0f;
            #pragma unroll
            for (int o = 0; o < DOUT; o++) s += expf(l[o] - mx);
            const float ls = logf(s);
            #pragma unroll
            for (int o = 0; o < DOUT; o++)
                out[(size_t)(m0p + tid) * DOUT + o] = l[o] - mx - ls;
        }
        __syncthreads();
    }
}

// ---------------------------------------------------------------------------
extern "C" void kernel_launch(void* const* d_in, const int* in_sizes, int n_in,
                              void* d_out, int out_size) {
    const float* x  = (const float*)d_in[0];
    const float* w1 = (const float*)d_in[1];
    const float* b1 = (const float*)d_in[2];
    const float* w2 = (const float*)d_in[3];
    const float* b2 = (const float*)d_in[4];
    float* out = (float*)d_out;

    cudaFuncSetAttribute(fused_kernel,
                         cudaFuncAttributeMaxDynamicSharedMemorySize, G1_SMEM);

    int nsm = 0;
    cudaDeviceGetAttribute(&nsm, cudaDevAttrMultiProcessorCount, 0);
    if (nsm <= 0) nsm = 148;                 // safe fallback (all CTAs resident)

    transpose_x_kernel<<<dim3(B_ / 32, (DIN + 31) / 32), 256>>>(x);  // launch 0
    build_w2scan_kernel<<<1, 1024>>>(w2);    // launch 1 (slots + maxbits + bar)
    build_w1_kernel<<<DH / 8, 256>>>(w1);    // launch 2 (reads g_slot)
    fused_kernel<<<nsm, 1024, G1_SMEM>>>(b1, b2, out);   // launch 3 (ncu slot)
}